// round 1
// baseline (speedup 1.0000x reference)
#include <cuda_runtime.h>
#include <math.h>

#define NEG_SLOPE 0.2f
#define KNN_K 20
#define BATCH 8
#define NPTS 2048
#define CO 64
#define CIN 6
#define ROWS (CO*CIN)   // 384

// scratch: knn indices
__device__ int g_knn[BATCH * NPTS * KNN_K];

// ---------------------------------------------------------------------------
// Kernel 1: brute-force KNN (top-K of pd = 2*dot - xx_i - xx_j) per batch.
// 128 blocks x 128 threads; block b= blockIdx/16 handles 128 points of batch.
// ---------------------------------------------------------------------------
__global__ __launch_bounds__(128) void knn_kernel(const float* __restrict__ x) {
    __shared__ float sx0[NPTS], sx1[NPTS], sx2[NPTS], sxx[NPTS];
    const int b = blockIdx.x >> 4;
    const float* xb = x + (size_t)b * 3 * NPTS;
    for (int j = threadIdx.x; j < NPTS; j += 128) {
        float a0 = xb[j], a1 = xb[NPTS + j], a2 = xb[2 * NPTS + j];
        sx0[j] = a0; sx1[j] = a1; sx2[j] = a2;
        // match reference: xx = sum(x*x) as squares then adds
        sxx[j] = (a0 * a0 + a1 * a1) + a2 * a2;
    }
    __syncthreads();

    const int i = ((blockIdx.x & 15) << 7) + threadIdx.x;
    const float c0 = sx0[i], c1 = sx1[i], c2 = sx2[i];
    const float cxx = sxx[i];

    float bestd[KNN_K];
    int besti[KNN_K];
#pragma unroll
    for (int k = 0; k < KNN_K; k++) { bestd[k] = -INFINITY; besti[k] = 0; }

#pragma unroll 4
    for (int j = 0; j < NPTS; j++) {
        float d = c0 * sx0[j];
        d = fmaf(c1, sx1[j], d);
        d = fmaf(c2, sx2[j], d);
        d = 2.0f * d - cxx - sxx[j];
        if (d > bestd[KNN_K - 1]) {
            int p = KNN_K - 1;
            while (p > 0 && bestd[p - 1] < d) {
                bestd[p] = bestd[p - 1]; besti[p] = besti[p - 1]; p--;
            }
            bestd[p] = d; besti[p] = j;
        }
    }
    int* out = g_knn + ((size_t)b * NPTS + i) * KNN_K;
#pragma unroll
    for (int k = 0; k < KNN_K; k++) out[k] = besti[k];
}

// ---------------------------------------------------------------------------
// Kernel 2: fused edge-feature -> MLP0 -> MLP1 bilinear -> max_k -> head.
// One block = 8 points, 512 threads. thread t: pt = t>>6, o = t&63.
// smem layout (floats):
//   sW1i [6][64p][64o]   24576   (W1[o*6+i][p] transposed for conflict-free o)
//   sY   [8][64p][20k]   10240
//   sE   [8][20][6]        960
//   sW0  [64][6]           384
//   sB0s,sB0b,sB1s,sB1b  4*64
//   sWc  [3][64]           192
//   sBnc [8]                 8  (3 scale + 3 bias, padded)
//   sX1  [8][64]           512
// ---------------------------------------------------------------------------
#define PTS 8
#define THR 512

#define OFF_W1   0
#define OFF_Y    (OFF_W1 + 24576)
#define OFF_E    (OFF_Y + 10240)
#define OFF_W0   (OFF_E + 960)
#define OFF_B0S  (OFF_W0 + 384)
#define OFF_B0B  (OFF_B0S + 64)
#define OFF_B1S  (OFF_B0B + 64)
#define OFF_B1B  (OFF_B1S + 64)
#define OFF_WC   (OFF_B1B + 64)
#define OFF_BNC  (OFF_WC + 192)
#define OFF_X1   (OFF_BNC + 8)
#define SMEM_FLOATS (OFF_X1 + 512)
#define SMEM_BYTES (SMEM_FLOATS * 4)

__global__ __launch_bounds__(THR, 1) void edge_kernel(
    const float* __restrict__ x,
    const float* __restrict__ W0,
    const float* __restrict__ bn0_s, const float* __restrict__ bn0_b,
    const float* __restrict__ W1,
    const float* __restrict__ bn1_s, const float* __restrict__ bn1_b,
    const float* __restrict__ Wc,
    const float* __restrict__ bnc_s, const float* __restrict__ bnc_b,
    float* __restrict__ outp)
{
    extern __shared__ float sm[];
    float* sW1i = sm + OFF_W1;
    float* sY   = sm + OFF_Y;
    float* sE   = sm + OFF_E;
    float* sW0  = sm + OFF_W0;
    float* sB0s = sm + OFF_B0S;
    float* sB0b = sm + OFF_B0B;
    float* sB1s = sm + OFF_B1S;
    float* sB1b = sm + OFF_B1B;
    float* sWc  = sm + OFF_WC;
    float* sBnc = sm + OFF_BNC;
    float* sX1  = sm + OFF_X1;

    const int t = threadIdx.x;
    const int gid0 = blockIdx.x * PTS;

    // stage W1 transposed: sW1i[(ii*64 + p)*64 + oo] = W1[(oo*6+ii)*64 + p]
    for (int g = t; g < ROWS * CO; g += THR) {
        int q = g >> 6;          // row 0..383
        int p = g & 63;
        int oo = q / 6;
        int ii = q - oo * 6;
        sW1i[(ii * 64 + p) * 64 + oo] = W1[g];
    }
    if (t < 384) sW0[t] = W0[t];
    if (t < 64) {
        sB0s[t] = bn0_s[t]; sB0b[t] = bn0_b[t];
        sB1s[t] = bn1_s[t]; sB1b[t] = bn1_b[t];
    }
    if (t < 192) sWc[t] = Wc[t];
    if (t < 3) { sBnc[t] = bnc_s[t]; sBnc[4 + t] = bnc_b[t]; }

    // edge features e = [nbr - ctr, ctr]
    if (t < PTS * KNN_K) {
        int pt = t / KNN_K, k = t - pt * KNN_K;
        int gid = gid0 + pt;
        int b = gid >> 11, n = gid & (NPTS - 1);
        const float* xb = x + (size_t)b * 3 * NPTS;
        float c0 = xb[n], c1 = xb[NPTS + n], c2 = xb[2 * NPTS + n];
        int j = g_knn[((size_t)b * NPTS + n) * KNN_K + k];
        float* e = sE + (pt * KNN_K + k) * 6;
        e[0] = xb[j] - c0;
        e[1] = xb[NPTS + j] - c1;
        e[2] = xb[2 * NPTS + j] - c2;
        e[3] = c0; e[4] = c1; e[5] = c2;
    }
    __syncthreads();

    // y[pt][p][k] = leaky((e . W0[p]) * bn0_s[p] + bn0_b[p])
    for (int v = t; v < PTS * CO * KNN_K; v += THR) {
        int pt = v / (CO * KNN_K);
        int rem = v - pt * (CO * KNN_K);
        int p = rem / KNN_K;
        int k = rem - p * KNN_K;
        const float* e = sE + (pt * KNN_K + k) * 6;
        const float* w = sW0 + p * 6;
        float d = e[0] * w[0];
        d = fmaf(e[1], w[1], d);
        d = fmaf(e[2], w[2], d);
        d = fmaf(e[3], w[3], d);
        d = fmaf(e[4], w[4], d);
        d = fmaf(e[5], w[5], d);
        float yv = fmaf(d, sB0s[p], sB0b[p]);
        yv = (yv >= 0.0f) ? yv : NEG_SLOPE * yv;
        sY[(pt * CO + p) * KNN_K + k] = yv;
    }
    __syncthreads();

    // main bilinear GEMM + leaky + max over k
    {
        const int pt = t >> 6;
        const int o  = t & 63;
        const float* ybase = sY + pt * CO * KNN_K;
        const float b1s = sB1s[o], b1b = sB1b[o];
        float maxv = -INFINITY;

#pragma unroll
        for (int kc = 0; kc < KNN_K; kc += 4) {
            float acc[4][6];
#pragma unroll
            for (int kk = 0; kk < 4; kk++)
#pragma unroll
                for (int ii = 0; ii < 6; ii++) acc[kk][ii] = 0.0f;

            const float* yk = ybase + kc;
#pragma unroll 4
            for (int p = 0; p < CO; p++) {
                float4 y4 = *(const float4*)(yk + p * KNN_K);
                const float* wp = sW1i + p * 64 + o;
#pragma unroll
                for (int ii = 0; ii < 6; ii++) {
                    float w = wp[ii * 4096];
                    acc[0][ii] = fmaf(y4.x, w, acc[0][ii]);
                    acc[1][ii] = fmaf(y4.y, w, acc[1][ii]);
                    acc[2][ii] = fmaf(y4.z, w, acc[2][ii]);
                    acc[3][ii] = fmaf(y4.w, w, acc[3][ii]);
                }
            }
#pragma unroll
            for (int kk = 0; kk < 4; kk++) {
                const float* e = sE + (pt * KNN_K + kc + kk) * 6;
                float oa = acc[kk][0] * e[0];
                oa = fmaf(acc[kk][1], e[1], oa);
                oa = fmaf(acc[kk][2], e[2], oa);
                oa = fmaf(acc[kk][3], e[3], oa);
                oa = fmaf(acc[kk][4], e[4], oa);
                oa = fmaf(acc[kk][5], e[5], oa);
                float vv = fmaf(oa, b1s, b1b);
                vv = (vv >= 0.0f) ? vv : NEG_SLOPE * vv;
                maxv = fmaxf(maxv, vv);
            }
        }
        sX1[pt * 64 + o] = maxv;
    }
    __syncthreads();

    // head: z[c] = leaky((x1 . Wc[c]) * bnc_s[c] + bnc_b[c]) -> out[b][c][n]
    if (t < PTS * 3) {
        int pt = t / 3, c = t - pt * 3;
        int gid = gid0 + pt;
        int b = gid >> 11, n = gid & (NPTS - 1);
        const float* x1 = sX1 + pt * 64;
        const float* w = sWc + c * 64;
        float d = 0.0f;
#pragma unroll
        for (int o = 0; o < 64; o++) d = fmaf(x1[o], w[o], d);
        float z = fmaf(d, sBnc[c], sBnc[4 + c]);
        z = (z >= 0.0f) ? z : NEG_SLOPE * z;
        outp[((size_t)b * 3 + c) * NPTS + n] = z;
    }
}

// ---------------------------------------------------------------------------
extern "C" void kernel_launch(void* const* d_in, const int* in_sizes, int n_in,
                              void* d_out, int out_size)
{
    const float* x     = (const float*)d_in[0];
    const float* W0    = (const float*)d_in[1];
    const float* bn0_s = (const float*)d_in[2];
    const float* bn0_b = (const float*)d_in[3];
    const float* W1    = (const float*)d_in[4];
    const float* bn1_s = (const float*)d_in[5];
    const float* bn1_b = (const float*)d_in[6];
    const float* Wc    = (const float*)d_in[7];
    const float* bnc_s = (const float*)d_in[8];
    const float* bnc_b = (const float*)d_in[9];
    float* outp = (float*)d_out;

    cudaFuncSetAttribute(edge_kernel,
                         cudaFuncAttributeMaxDynamicSharedMemorySize, SMEM_BYTES);

    knn_kernel<<<128, 128>>>(x);
    edge_kernel<<<(BATCH * NPTS) / PTS, THR, SMEM_BYTES>>>(
        x, W0, bn0_s, bn0_b, W1, bn1_s, bn1_b, Wc, bnc_s, bnc_b, outp);
}

// round 2
// speedup vs baseline: 1.3302x; 1.3302x over previous
#include <cuda_runtime.h>
#include <math.h>

#define NEG_SLOPE 0.2f
#define KNN_K 20
#define BATCH 8
#define NPTS 2048
#define CO 64
#define CIN 6
#define ROWS (CO*CIN)   // 384

__device__ int g_knn[BATCH * NPTS * KNN_K];

// ---------------------------------------------------------------------------
// f32x2 helpers (packed dual-FMA, sm_103a)
// ---------------------------------------------------------------------------
__device__ __forceinline__ void ffma2(unsigned long long& d,
                                      unsigned long long a,
                                      unsigned long long b) {
    asm("fma.rn.f32x2 %0, %1, %2, %0;" : "+l"(d) : "l"(a), "l"(b));
}
__device__ __forceinline__ unsigned long long dup2(float w) {
    unsigned long long r;
    asm("mov.b64 %0, {%1, %1};" : "=l"(r) : "f"(w));
    return r;
}
__device__ __forceinline__ void unpack2(float& lo, float& hi, unsigned long long v) {
    asm("mov.b64 {%0, %1}, %2;" : "=f"(lo), "=f"(hi) : "l"(v));
}

// ---------------------------------------------------------------------------
// Kernel 1: brute-force KNN, register-resident top-K via unrolled
// predicated compare-swap chain (no dynamic indexing -> no local memory).
// ---------------------------------------------------------------------------
__global__ __launch_bounds__(128) void knn_kernel(const float* __restrict__ x) {
    __shared__ float sx0[NPTS], sx1[NPTS], sx2[NPTS], sxx[NPTS];
    const int b = blockIdx.x >> 4;
    const float* xb = x + (size_t)b * 3 * NPTS;
    for (int j = threadIdx.x; j < NPTS; j += 128) {
        float a0 = xb[j], a1 = xb[NPTS + j], a2 = xb[2 * NPTS + j];
        sx0[j] = a0; sx1[j] = a1; sx2[j] = a2;
        sxx[j] = (a0 * a0 + a1 * a1) + a2 * a2;
    }
    __syncthreads();

    const int i = ((blockIdx.x & 15) << 7) + threadIdx.x;
    const float c0 = sx0[i], c1 = sx1[i], c2 = sx2[i];
    const float cxx = sxx[i];

    float bestd[KNN_K];
    int besti[KNN_K];
#pragma unroll
    for (int k = 0; k < KNN_K; k++) { bestd[k] = -INFINITY; besti[k] = 0; }

#pragma unroll 4
    for (int j = 0; j < NPTS; j++) {
        float d = c0 * sx0[j];
        d = fmaf(c1, sx1[j], d);
        d = fmaf(c2, sx2[j], d);
        d = 2.0f * d - cxx - sxx[j];
        if (d > bestd[KNN_K - 1]) {
            float cd = d; int ci = j;
#pragma unroll
            for (int k = 0; k < KNN_K; k++) {
                bool sw = cd > bestd[k];
                float td = bestd[k]; int ti = besti[k];
                if (sw) { bestd[k] = cd; besti[k] = ci; cd = td; ci = ti; }
            }
        }
    }
    int* out = g_knn + ((size_t)b * NPTS + i) * KNN_K;
#pragma unroll
    for (int k = 0; k < KNN_K; k++) out[k] = besti[k];
}

// ---------------------------------------------------------------------------
// Kernel 2: fused edge-feature -> MLP0 -> MLP1 bilinear (f32x2) -> max_k -> head
// One block = 8 points, 512 threads. thread t: pt = t>>6, o = t&63.
// ---------------------------------------------------------------------------
#define PTS 8
#define THR 512

#define OFF_W1   0
#define OFF_Y    (OFF_W1 + 24576)
#define OFF_E    (OFF_Y + 10240)
#define OFF_W0   (OFF_E + 960)
#define OFF_B0S  (OFF_W0 + 384)
#define OFF_B0B  (OFF_B0S + 64)
#define OFF_B1S  (OFF_B0B + 64)
#define OFF_B1B  (OFF_B1S + 64)
#define OFF_WC   (OFF_B1B + 64)
#define OFF_BNC  (OFF_WC + 192)
#define OFF_X1   (OFF_BNC + 8)
#define SMEM_FLOATS (OFF_X1 + 512)
#define SMEM_BYTES (SMEM_FLOATS * 4)

__global__ __launch_bounds__(THR, 1) void edge_kernel(
    const float* __restrict__ x,
    const float* __restrict__ W0,
    const float* __restrict__ bn0_s, const float* __restrict__ bn0_b,
    const float* __restrict__ W1,
    const float* __restrict__ bn1_s, const float* __restrict__ bn1_b,
    const float* __restrict__ Wc,
    const float* __restrict__ bnc_s, const float* __restrict__ bnc_b,
    float* __restrict__ outp)
{
    extern __shared__ float sm[];
    float* sW1i = sm + OFF_W1;   // [ii][p][o] : 6 x 64 x 64
    float* sY   = sm + OFF_Y;    // [pt][p][k] : 8 x 64 x 20
    float* sE   = sm + OFF_E;    // [pt][k][6]
    float* sW0  = sm + OFF_W0;
    float* sB0s = sm + OFF_B0S;
    float* sB0b = sm + OFF_B0B;
    float* sB1s = sm + OFF_B1S;
    float* sB1b = sm + OFF_B1B;
    float* sWc  = sm + OFF_WC;
    float* sBnc = sm + OFF_BNC;
    float* sX1  = sm + OFF_X1;

    const int t = threadIdx.x;
    const int gid0 = blockIdx.x * PTS;

    for (int g = t; g < ROWS * CO; g += THR) {
        int q = g >> 6;
        int p = g & 63;
        int oo = q / 6;
        int ii = q - oo * 6;
        sW1i[(ii * 64 + p) * 64 + oo] = W1[g];
    }
    if (t < 384) sW0[t] = W0[t];
    if (t < 64) {
        sB0s[t] = bn0_s[t]; sB0b[t] = bn0_b[t];
        sB1s[t] = bn1_s[t]; sB1b[t] = bn1_b[t];
    }
    if (t < 192) sWc[t] = Wc[t];
    if (t < 3) { sBnc[t] = bnc_s[t]; sBnc[4 + t] = bnc_b[t]; }

    if (t < PTS * KNN_K) {
        int pt = t / KNN_K, k = t - pt * KNN_K;
        int gid = gid0 + pt;
        int b = gid >> 11, n = gid & (NPTS - 1);
        const float* xb = x + (size_t)b * 3 * NPTS;
        float c0 = xb[n], c1 = xb[NPTS + n], c2 = xb[2 * NPTS + n];
        int j = g_knn[((size_t)b * NPTS + n) * KNN_K + k];
        float* e = sE + (pt * KNN_K + k) * 6;
        e[0] = xb[j] - c0;
        e[1] = xb[NPTS + j] - c1;
        e[2] = xb[2 * NPTS + j] - c2;
        e[3] = c0; e[4] = c1; e[5] = c2;
    }
    __syncthreads();

    // y[pt][p][k] = leaky((e . W0[p]) * bn0_s[p] + bn0_b[p])
    for (int v = t; v < PTS * CO * KNN_K; v += THR) {
        int pt = v / (CO * KNN_K);
        int rem = v - pt * (CO * KNN_K);
        int p = rem / KNN_K;
        int k = rem - p * KNN_K;
        const float* e = sE + (pt * KNN_K + k) * 6;
        const float* w = sW0 + p * 6;
        float d = e[0] * w[0];
        d = fmaf(e[1], w[1], d);
        d = fmaf(e[2], w[2], d);
        d = fmaf(e[3], w[3], d);
        d = fmaf(e[4], w[4], d);
        d = fmaf(e[5], w[5], d);
        float yv = fmaf(d, sB0s[p], sB0b[p]);
        yv = (yv >= 0.0f) ? yv : NEG_SLOPE * yv;
        sY[(pt * CO + p) * KNN_K + k] = yv;
    }
    __syncthreads();

    // main bilinear GEMM via packed f32x2, two halves of 10 k each
    {
        const int pt = t >> 6;
        const int o  = t & 63;
        const float b1s = sB1s[o], b1b = sB1b[o];
        float maxv = -INFINITY;

#pragma unroll
        for (int half = 0; half < 2; half++) {
            unsigned long long acc[5][6];
#pragma unroll
            for (int q = 0; q < 5; q++)
#pragma unroll
                for (int ii = 0; ii < 6; ii++) acc[q][ii] = 0ull;

            const float* ybase = sY + pt * CO * KNN_K + half * 10;

#pragma unroll 4
            for (int p = 0; p < CO; p++) {
                const unsigned long long* yp =
                    (const unsigned long long*)(ybase + p * KNN_K);
                unsigned long long y01 = yp[0];
                unsigned long long y23 = yp[1];
                unsigned long long y45 = yp[2];
                unsigned long long y67 = yp[3];
                unsigned long long y89 = yp[4];
                const float* wp = sW1i + p * 64 + o;
#pragma unroll
                for (int ii = 0; ii < 6; ii++) {
                    unsigned long long wd = dup2(wp[ii * 4096]);
                    ffma2(acc[0][ii], y01, wd);
                    ffma2(acc[1][ii], y23, wd);
                    ffma2(acc[2][ii], y45, wd);
                    ffma2(acc[3][ii], y67, wd);
                    ffma2(acc[4][ii], y89, wd);
                }
            }

#pragma unroll
            for (int q = 0; q < 5; q++) {
                float alo[6], ahi[6];
#pragma unroll
                for (int ii = 0; ii < 6; ii++) unpack2(alo[ii], ahi[ii], acc[q][ii]);

                const float* e0 = sE + (pt * KNN_K + half * 10 + 2 * q) * 6;
                const float* e1 = e0 + 6;

                float oa = alo[0] * e0[0];
                oa = fmaf(alo[1], e0[1], oa);
                oa = fmaf(alo[2], e0[2], oa);
                oa = fmaf(alo[3], e0[3], oa);
                oa = fmaf(alo[4], e0[4], oa);
                oa = fmaf(alo[5], e0[5], oa);
                float vv = fmaf(oa, b1s, b1b);
                vv = (vv >= 0.0f) ? vv : NEG_SLOPE * vv;
                maxv = fmaxf(maxv, vv);

                float ob = ahi[0] * e1[0];
                ob = fmaf(ahi[1], e1[1], ob);
                ob = fmaf(ahi[2], e1[2], ob);
                ob = fmaf(ahi[3], e1[3], ob);
                ob = fmaf(ahi[4], e1[4], ob);
                ob = fmaf(ahi[5], e1[5], ob);
                float vw = fmaf(ob, b1s, b1b);
                vw = (vw >= 0.0f) ? vw : NEG_SLOPE * vw;
                maxv = fmaxf(maxv, vw);
            }
        }
        sX1[pt * 64 + o] = maxv;
    }
    __syncthreads();

    if (t < PTS * 3) {
        int pt = t / 3, c = t - pt * 3;
        int gid = gid0 + pt;
        int b = gid >> 11, n = gid & (NPTS - 1);
        const float* x1 = sX1 + pt * 64;
        const float* w = sWc + c * 64;
        float d = 0.0f;
#pragma unroll
        for (int o = 0; o < 64; o++) d = fmaf(x1[o], w[o], d);
        float z = fmaf(d, sBnc[c], sBnc[4 + c]);
        z = (z >= 0.0f) ? z : NEG_SLOPE * z;
        outp[((size_t)b * 3 + c) * NPTS + n] = z;
    }
}

// ---------------------------------------------------------------------------
extern "C" void kernel_launch(void* const* d_in, const int* in_sizes, int n_in,
                              void* d_out, int out_size)
{
    const float* x     = (const float*)d_in[0];
    const float* W0    = (const float*)d_in[1];
    const float* bn0_s = (const float*)d_in[2];
    const float* bn0_b = (const float*)d_in[3];
    const float* W1    = (const float*)d_in[4];
    const float* bn1_s = (const float*)d_in[5];
    const float* bn1_b = (const float*)d_in[6];
    const float* Wc    = (const float*)d_in[7];
    const float* bnc_s = (const float*)d_in[8];
    const float* bnc_b = (const float*)d_in[9];
    float* outp = (float*)d_out;

    cudaFuncSetAttribute(edge_kernel,
                         cudaFuncAttributeMaxDynamicSharedMemorySize, SMEM_BYTES);

    knn_kernel<<<128, 128>>>(x);
    edge_kernel<<<(BATCH * NPTS) / PTS, THR, SMEM_BYTES>>>(
        x, W0, bn0_s, bn0_b, W1, bn1_s, bn1_b, Wc, bnc_s, bnc_b, outp);
}

// round 3
// speedup vs baseline: 1.4259x; 1.0719x over previous
#include <cuda_runtime.h>
#include <math.h>

#define NEG_SLOPE 0.2f
#define KNN_K 20
#define BATCH 8
#define NPTS 2048
#define CO 64
#define CIN 6
#define ROWS (CO*CIN)   // 384

__device__ int g_knn[BATCH * NPTS * KNN_K];

// ---------------------------------------------------------------------------
// f32x2 helpers (packed dual-FMA, sm_103a)
// ---------------------------------------------------------------------------
__device__ __forceinline__ void ffma2(unsigned long long& d,
                                      unsigned long long a,
                                      unsigned long long b) {
    asm("fma.rn.f32x2 %0, %1, %2, %0;" : "+l"(d) : "l"(a), "l"(b));
}
__device__ __forceinline__ unsigned long long dup2(float w) {
    unsigned long long r;
    asm("mov.b64 %0, {%1, %1};" : "=l"(r) : "f"(w));
    return r;
}
__device__ __forceinline__ void unpack2(float& lo, float& hi, unsigned long long v) {
    asm("mov.b64 {%0, %1}, %2;" : "=f"(lo), "=f"(hi) : "l"(v));
}

// ---------------------------------------------------------------------------
// Kernel 1: brute-force KNN. 4 threads per point, each scans a contiguous
// 512-j segment keeping a register top-20 (static compare-swap chain),
// then seg 0 merges the other 3 sorted lists from smem.
// 256 blocks x 256 threads -> ~14 warps/SM.
// ---------------------------------------------------------------------------
#define KNN_THR 256
#define KNN_PPB 64
#define KSEG 4
#define SEGLEN (NPTS / KSEG)   // 512

// dynamic smem floats: sx0,sx1,sx2,sxx (4*2048) + cd (64*80) ; ints ci (64*80)
#define KOFF_X0  0
#define KOFF_X1  (KOFF_X0 + NPTS)
#define KOFF_X2  (KOFF_X1 + NPTS)
#define KOFF_XX  (KOFF_X2 + NPTS)
#define KOFF_CD  (KOFF_XX + NPTS)
#define KOFF_CI  (KOFF_CD + KNN_PPB * KSEG * KNN_K)
#define KNN_SMEM_FLOATS (KOFF_CI + KNN_PPB * KSEG * KNN_K)
#define KNN_SMEM_BYTES (KNN_SMEM_FLOATS * 4)

__global__ __launch_bounds__(KNN_THR) void knn_kernel(const float* __restrict__ x) {
    extern __shared__ float ksm[];
    float* sx0 = ksm + KOFF_X0;
    float* sx1 = ksm + KOFF_X1;
    float* sx2 = ksm + KOFF_X2;
    float* sxx = ksm + KOFF_XX;
    float* cd  = ksm + KOFF_CD;
    int*   ci  = (int*)(ksm + KOFF_CI);

    const int b = blockIdx.x >> 5;           // batch
    const int chunk = blockIdx.x & 31;       // 64-point chunk within batch
    const float* xb = x + (size_t)b * 3 * NPTS;

    const int t = threadIdx.x;
    for (int j = t; j < NPTS; j += KNN_THR) {
        float a0 = xb[j], a1 = xb[NPTS + j], a2 = xb[2 * NPTS + j];
        sx0[j] = a0; sx1[j] = a1; sx2[j] = a2;
        sxx[j] = (a0 * a0 + a1 * a1) + a2 * a2;
    }
    __syncthreads();

    const int s  = t >> 6;        // segment 0..3 (warp-uniform)
    const int pp = t & 63;        // point within chunk
    const int i  = (chunk << 6) + pp;

    const float c0 = sx0[i], c1 = sx1[i], c2 = sx2[i];
    const float cxx = sxx[i];

    float bestd[KNN_K];
    int besti[KNN_K];
#pragma unroll
    for (int k = 0; k < KNN_K; k++) { bestd[k] = -INFINITY; besti[k] = 0; }

    const int j0 = s * SEGLEN;
#pragma unroll 4
    for (int jj = 0; jj < SEGLEN; jj++) {
        int j = j0 + jj;
        float d = c0 * sx0[j];
        d = fmaf(c1, sx1[j], d);
        d = fmaf(c2, sx2[j], d);
        d = 2.0f * d - cxx - sxx[j];
        if (d > bestd[KNN_K - 1]) {
            float cdv = d; int civ = j;
#pragma unroll
            for (int k = 0; k < KNN_K; k++) {
                bool sw = cdv > bestd[k];
                float td = bestd[k]; int ti = besti[k];
                if (sw) { bestd[k] = cdv; besti[k] = civ; cdv = td; civ = ti; }
            }
        }
    }

    // stash per-segment lists
    {
        float* cdp = cd + (pp * KSEG + s) * KNN_K;
        int*   cip = ci + (pp * KSEG + s) * KNN_K;
#pragma unroll
        for (int k = 0; k < KNN_K; k++) { cdp[k] = bestd[k]; cip[k] = besti[k]; }
    }
    __syncthreads();

    // segment 0 threads merge segments 1..3 (ascending j => strict-> keeps
    // lower-index-first tie order, matching jax top_k)
    if (s == 0) {
        for (int ss = 1; ss < KSEG; ss++) {
            const float* cdp = cd + (pp * KSEG + ss) * KNN_K;
            const int*   cip = ci + (pp * KSEG + ss) * KNN_K;
#pragma unroll
            for (int k = 0; k < KNN_K; k++) {
                float d = cdp[k]; int jx = cip[k];
                if (d > bestd[KNN_K - 1]) {
                    float cdv = d; int civ = jx;
#pragma unroll
                    for (int q = 0; q < KNN_K; q++) {
                        bool sw = cdv > bestd[q];
                        float td = bestd[q]; int ti = besti[q];
                        if (sw) { bestd[q] = cdv; besti[q] = civ; cdv = td; civ = ti; }
                    }
                }
            }
        }
        int* out = g_knn + ((size_t)b * NPTS + i) * KNN_K;
#pragma unroll
        for (int k = 0; k < KNN_K; k++) out[k] = besti[k];
    }
}

// ---------------------------------------------------------------------------
// Kernel 2: fused edge-feature -> MLP0 -> MLP1 bilinear (f32x2) -> max_k -> head
// One block = 8 points, 512 threads. thread t: pt = t>>6, o = t&63.
// ---------------------------------------------------------------------------
#define PTS 8
#define THR 512

#define OFF_W1   0
#define OFF_Y    (OFF_W1 + 24576)
#define OFF_E    (OFF_Y + 10240)
#define OFF_W0   (OFF_E + 960)
#define OFF_B0S  (OFF_W0 + 384)
#define OFF_B0B  (OFF_B0S + 64)
#define OFF_B1S  (OFF_B0B + 64)
#define OFF_B1B  (OFF_B1S + 64)
#define OFF_WC   (OFF_B1B + 64)
#define OFF_BNC  (OFF_WC + 192)
#define OFF_X1   (OFF_BNC + 8)
#define SMEM_FLOATS (OFF_X1 + 512)
#define SMEM_BYTES (SMEM_FLOATS * 4)

__global__ __launch_bounds__(THR, 1) void edge_kernel(
    const float* __restrict__ x,
    const float* __restrict__ W0,
    const float* __restrict__ bn0_s, const float* __restrict__ bn0_b,
    const float* __restrict__ W1,
    const float* __restrict__ bn1_s, const float* __restrict__ bn1_b,
    const float* __restrict__ Wc,
    const float* __restrict__ bnc_s, const float* __restrict__ bnc_b,
    float* __restrict__ outp)
{
    extern __shared__ float sm[];
    float* sW1i = sm + OFF_W1;   // [ii][p][o] : 6 x 64 x 64
    float* sY   = sm + OFF_Y;    // [pt][p][k] : 8 x 64 x 20
    float* sE   = sm + OFF_E;    // [pt][k][6]
    float* sW0  = sm + OFF_W0;
    float* sB0s = sm + OFF_B0S;
    float* sB0b = sm + OFF_B0B;
    float* sB1s = sm + OFF_B1S;
    float* sB1b = sm + OFF_B1B;
    float* sWc  = sm + OFF_WC;
    float* sBnc = sm + OFF_BNC;
    float* sX1  = sm + OFF_X1;

    const int t = threadIdx.x;
    const int gid0 = blockIdx.x * PTS;

    for (int g = t; g < ROWS * CO; g += THR) {
        int q = g >> 6;
        int p = g & 63;
        int oo = q / 6;
        int ii = q - oo * 6;
        sW1i[(ii * 64 + p) * 64 + oo] = W1[g];
    }
    if (t < 384) sW0[t] = W0[t];
    if (t < 64) {
        sB0s[t] = bn0_s[t]; sB0b[t] = bn0_b[t];
        sB1s[t] = bn1_s[t]; sB1b[t] = bn1_b[t];
    }
    if (t < 192) sWc[t] = Wc[t];
    if (t < 3) { sBnc[t] = bnc_s[t]; sBnc[4 + t] = bnc_b[t]; }

    if (t < PTS * KNN_K) {
        int pt = t / KNN_K, k = t - pt * KNN_K;
        int gid = gid0 + pt;
        int b = gid >> 11, n = gid & (NPTS - 1);
        const float* xb = x + (size_t)b * 3 * NPTS;
        float c0 = xb[n], c1 = xb[NPTS + n], c2 = xb[2 * NPTS + n];
        int j = g_knn[((size_t)b * NPTS + n) * KNN_K + k];
        float* e = sE + (pt * KNN_K + k) * 6;
        e[0] = xb[j] - c0;
        e[1] = xb[NPTS + j] - c1;
        e[2] = xb[2 * NPTS + j] - c2;
        e[3] = c0; e[4] = c1; e[5] = c2;
    }
    __syncthreads();

    // y[pt][p][k] = leaky((e . W0[p]) * bn0_s[p] + bn0_b[p])
    for (int v = t; v < PTS * CO * KNN_K; v += THR) {
        int pt = v / (CO * KNN_K);
        int rem = v - pt * (CO * KNN_K);
        int p = rem / KNN_K;
        int k = rem - p * KNN_K;
        const float* e = sE + (pt * KNN_K + k) * 6;
        const float* w = sW0 + p * 6;
        float d = e[0] * w[0];
        d = fmaf(e[1], w[1], d);
        d = fmaf(e[2], w[2], d);
        d = fmaf(e[3], w[3], d);
        d = fmaf(e[4], w[4], d);
        d = fmaf(e[5], w[5], d);
        float yv = fmaf(d, sB0s[p], sB0b[p]);
        yv = (yv >= 0.0f) ? yv : NEG_SLOPE * yv;
        sY[(pt * CO + p) * KNN_K + k] = yv;
    }
    __syncthreads();

    // main bilinear GEMM via packed f32x2, two halves of 10 k each
    {
        const int pt = t >> 6;
        const int o  = t & 63;
        const float b1s = sB1s[o], b1b = sB1b[o];
        float maxv = -INFINITY;

#pragma unroll
        for (int half = 0; half < 2; half++) {
            unsigned long long acc[5][6];
#pragma unroll
            for (int q = 0; q < 5; q++)
#pragma unroll
                for (int ii = 0; ii < 6; ii++) acc[q][ii] = 0ull;

            const float* ybase = sY + pt * CO * KNN_K + half * 10;

#pragma unroll 2
            for (int p = 0; p < CO; p++) {
                const unsigned long long* yp =
                    (const unsigned long long*)(ybase + p * KNN_K);
                unsigned long long y01 = yp[0];
                unsigned long long y23 = yp[1];
                unsigned long long y45 = yp[2];
                unsigned long long y67 = yp[3];
                unsigned long long y89 = yp[4];
                const float* wp = sW1i + p * 64 + o;
#pragma unroll
                for (int ii = 0; ii < 6; ii++) {
                    unsigned long long wd = dup2(wp[ii * 4096]);
                    ffma2(acc[0][ii], y01, wd);
                    ffma2(acc[1][ii], y23, wd);
                    ffma2(acc[2][ii], y45, wd);
                    ffma2(acc[3][ii], y67, wd);
                    ffma2(acc[4][ii], y89, wd);
                }
            }

#pragma unroll
            for (int q = 0; q < 5; q++) {
                float alo[6], ahi[6];
#pragma unroll
                for (int ii = 0; ii < 6; ii++) unpack2(alo[ii], ahi[ii], acc[q][ii]);

                const float* e0 = sE + (pt * KNN_K + half * 10 + 2 * q) * 6;
                const float* e1 = e0 + 6;

                float oa = alo[0] * e0[0];
                oa = fmaf(alo[1], e0[1], oa);
                oa = fmaf(alo[2], e0[2], oa);
                oa = fmaf(alo[3], e0[3], oa);
                oa = fmaf(alo[4], e0[4], oa);
                oa = fmaf(alo[5], e0[5], oa);
                float vv = fmaf(oa, b1s, b1b);
                vv = (vv >= 0.0f) ? vv : NEG_SLOPE * vv;
                maxv = fmaxf(maxv, vv);

                float ob = ahi[0] * e1[0];
                ob = fmaf(ahi[1], e1[1], ob);
                ob = fmaf(ahi[2], e1[2], ob);
                ob = fmaf(ahi[3], e1[3], ob);
                ob = fmaf(ahi[4], e1[4], ob);
                ob = fmaf(ahi[5], e1[5], ob);
                float vw = fmaf(ob, b1s, b1b);
                vw = (vw >= 0.0f) ? vw : NEG_SLOPE * vw;
                maxv = fmaxf(maxv, vw);
            }
        }
        sX1[pt * 64 + o] = maxv;
    }
    __syncthreads();

    if (t < PTS * 3) {
        int pt = t / 3, c = t - pt * 3;
        int gid = gid0 + pt;
        int b = gid >> 11, n = gid & (NPTS - 1);
        const float* x1 = sX1 + pt * 64;
        const float* w = sWc + c * 64;
        float d = 0.0f;
#pragma unroll
        for (int o = 0; o < 64; o++) d = fmaf(x1[o], w[o], d);
        float z = fmaf(d, sBnc[c], sBnc[4 + c]);
        z = (z >= 0.0f) ? z : NEG_SLOPE * z;
        outp[((size_t)b * 3 + c) * NPTS + n] = z;
    }
}

// ---------------------------------------------------------------------------
extern "C" void kernel_launch(void* const* d_in, const int* in_sizes, int n_in,
                              void* d_out, int out_size)
{
    const float* x     = (const float*)d_in[0];
    const float* W0    = (const float*)d_in[1];
    const float* bn0_s = (const float*)d_in[2];
    const float* bn0_b = (const float*)d_in[3];
    const float* W1    = (const float*)d_in[4];
    const float* bn1_s = (const float*)d_in[5];
    const float* bn1_b = (const float*)d_in[6];
    const float* Wc    = (const float*)d_in[7];
    const float* bnc_s = (const float*)d_in[8];
    const float* bnc_b = (const float*)d_in[9];
    float* outp = (float*)d_out;

    cudaFuncSetAttribute(knn_kernel,
                         cudaFuncAttributeMaxDynamicSharedMemorySize, KNN_SMEM_BYTES);
    cudaFuncSetAttribute(edge_kernel,
                         cudaFuncAttributeMaxDynamicSharedMemorySize, SMEM_BYTES);

    knn_kernel<<<BATCH * 32, KNN_THR, KNN_SMEM_BYTES>>>(x);
    edge_kernel<<<(BATCH * NPTS) / PTS, THR, SMEM_BYTES>>>(
        x, W0, bn0_s, bn0_b, W1, bn1_s, bn1_b, Wc, bnc_s, bnc_b, outp);
}

// round 5
// speedup vs baseline: 1.7974x; 1.2606x over previous
#include <cuda_runtime.h>
#include <math.h>
#include <stdint.h>

#define NEG_SLOPE 0.2f
#define KNN_K 20
#define BATCH 8
#define NPTS 2048
#define CO 64
#define CIN 6
#define ROWS 384
#define NPOINTS (BATCH * NPTS)

__device__ int g_knn[NPOINTS * KNN_K];

// ---------------------------------------------------------------------------
// f32x2 helpers
// ---------------------------------------------------------------------------
__device__ __forceinline__ void ffma2(unsigned long long& d,
                                      unsigned long long a,
                                      unsigned long long b) {
    asm("fma.rn.f32x2 %0, %1, %2, %0;" : "+l"(d) : "l"(a), "l"(b));
}
__device__ __forceinline__ unsigned long long dup2(float w) {
    unsigned long long r;
    asm("mov.b64 %0, {%1, %1};" : "=l"(r) : "f"(w));
    return r;
}
__device__ __forceinline__ unsigned long long pack2(float lo, float hi) {
    unsigned long long r;
    asm("mov.b64 %0, {%1, %2};" : "=l"(r) : "f"(lo), "f"(hi));
    return r;
}
__device__ __forceinline__ void unpack2(float& lo, float& hi, unsigned long long v) {
    asm("mov.b64 {%0, %1}, %2;" : "=f"(lo), "=f"(hi) : "l"(v));
}

// ---------------------------------------------------------------------------
// Kernel 1: brute-force KNN, float4-interleaved smem, 4 seg-threads/point.
// ---------------------------------------------------------------------------
#define KNN_THR 256
#define KNN_PPB 64
#define KSEG 4
#define SEGLEN (NPTS / KSEG)

#define KOFF_P   0
#define KOFF_CD  (NPTS * 4)
#define KOFF_CI  (KOFF_CD + KNN_PPB * KSEG * KNN_K)
#define KNN_SMEM_FLOATS (KOFF_CI + KNN_PPB * KSEG * KNN_K)
#define KNN_SMEM_BYTES (KNN_SMEM_FLOATS * 4)

__global__ __launch_bounds__(KNN_THR) void knn_kernel(const float* __restrict__ x) {
    extern __shared__ float ksm[];
    float4* sP = (float4*)(ksm + KOFF_P);
    float* cd = ksm + KOFF_CD;
    int*   ci = (int*)(ksm + KOFF_CI);

    const int b = blockIdx.x >> 5;
    const int chunk = blockIdx.x & 31;
    const float* xb = x + (size_t)b * 3 * NPTS;

    const int t = threadIdx.x;
    for (int j = t; j < NPTS; j += KNN_THR) {
        float a0 = xb[j], a1 = xb[NPTS + j], a2 = xb[2 * NPTS + j];
        float xx = (a0 * a0 + a1 * a1) + a2 * a2;
        sP[j] = make_float4(a0, a1, a2, xx);
    }
    __syncthreads();

    const int s  = t >> 6;
    const int pp = t & 63;
    const int i  = (chunk << 6) + pp;

    float4 cv = sP[i];
    const float c0 = cv.x, c1 = cv.y, c2 = cv.z, cxx = cv.w;

    float bestd[KNN_K];
    int besti[KNN_K];
#pragma unroll
    for (int k = 0; k < KNN_K; k++) { bestd[k] = -INFINITY; besti[k] = 0; }

    const int j0 = s * SEGLEN;
#pragma unroll 4
    for (int jj = 0; jj < SEGLEN; jj++) {
        int j = j0 + jj;
        float4 v = sP[j];
        float d = c0 * v.x;
        d = fmaf(c1, v.y, d);
        d = fmaf(c2, v.z, d);
        d = 2.0f * d - cxx - v.w;
        if (d > bestd[KNN_K - 1]) {
            float cdv = d; int civ = j;
#pragma unroll
            for (int k = 0; k < KNN_K; k++) {
                bool sw = cdv > bestd[k];
                float td = bestd[k]; int ti = besti[k];
                if (sw) { bestd[k] = cdv; besti[k] = civ; cdv = td; civ = ti; }
            }
        }
    }

    {
        float* cdp = cd + (pp * KSEG + s) * KNN_K;
        int*   cip = ci + (pp * KSEG + s) * KNN_K;
#pragma unroll
        for (int k = 0; k < KNN_K; k++) { cdp[k] = bestd[k]; cip[k] = besti[k]; }
    }
    __syncthreads();

    if (s == 0) {
        for (int ss = 1; ss < KSEG; ss++) {
            const float* cdp = cd + (pp * KSEG + ss) * KNN_K;
            const int*   cip = ci + (pp * KSEG + ss) * KNN_K;
#pragma unroll
            for (int k = 0; k < KNN_K; k++) {
                float d = cdp[k]; int jx = cip[k];
                if (d > bestd[KNN_K - 1]) {
                    float cdv = d; int civ = jx;
#pragma unroll
                    for (int q = 0; q < KNN_K; q++) {
                        bool sw = cdv > bestd[q];
                        float td = bestd[q]; int ti = besti[q];
                        if (sw) { bestd[q] = cdv; besti[q] = civ; cdv = td; civ = ti; }
                    }
                }
            }
        }
        int* out = g_knn + ((size_t)b * NPTS + i) * KNN_K;
#pragma unroll
        for (int k = 0; k < KNN_K; k++) out[k] = besti[k];
    }
}

// ---------------------------------------------------------------------------
// Kernel 2: fused edge kernel with c-folded bilinear GEMM (f32x2).
// 12 points/block, 768 threads; thread t: pt = t>>6, o = t&63.
// out[n,k,o] = sum_p y[k,p] * ( q[o,p] + sum_{i<3} W1[o,i,p] d_i[k] ),
//   q[o,p] = sum_{i>=3} W1[o,i,p] c_i   (k-independent).
// max over k BEFORE bn1+leaky (exact: bn1_s > 0).
// ---------------------------------------------------------------------------
#define PTS 12
#define THR 768
#define NTILES ((NPOINTS + PTS - 1) / PTS)

#define EPAD 9

#define F_W1A  0                       // [3][64p][64o] = 12288
#define F_W1B  (F_W1A + 12288)         // [3][64p][64o] = 12288
#define F_Y    (F_W1B + 12288)         // [12pt][64p][20k] = 15360
#define F_E    (F_Y + 15360)           // [12*20][9] = 2160
#define F_W0   (F_E + 2160)            // 384
#define F_B0S  (F_W0 + 384)
#define F_B0B  (F_B0S + 64)
#define F_B1S  (F_B0B + 64)
#define F_B1B  (F_B1S + 64)
#define F_WC   (F_B1B + 64)            // 192
#define F_BNC  (F_WC + 192)            // 8
#define F_X1   (F_BNC + 8)             // 768
#define SMEM_FLOATS (F_X1 + 768)
#define SMEM_BYTES (SMEM_FLOATS * 4)

__global__ __launch_bounds__(THR, 1) void edge_kernel(
    const float* __restrict__ x,
    const float* __restrict__ W0,
    const float* __restrict__ bn0_s, const float* __restrict__ bn0_b,
    const float* __restrict__ W1,
    const float* __restrict__ bn1_s, const float* __restrict__ bn1_b,
    const float* __restrict__ Wc,
    const float* __restrict__ bnc_s, const float* __restrict__ bnc_b,
    float* __restrict__ outp)
{
    extern __shared__ float sm[];
    float* sW1A = sm + F_W1A;
    float* sW1B = sm + F_W1B;
    float* sY   = sm + F_Y;
    float* sE   = sm + F_E;
    float* sW0  = sm + F_W0;
    float* sB0s = sm + F_B0S;
    float* sB0b = sm + F_B0B;
    float* sB1s = sm + F_B1S;
    float* sB1b = sm + F_B1B;
    float* sWc  = sm + F_WC;
    float* sBnc = sm + F_BNC;
    float* sX1  = sm + F_X1;

    const int t = threadIdx.x;
    const int tile = blockIdx.x;

    // stage W1 split: A (i<3) and B (i>=3), layout [i][p][o]
    for (int g = t; g < ROWS * CO; g += THR) {
        int q = g >> 6;          // row = oo*6 + ii
        int p = g & 63;
        int oo = q / 6;
        int ii = q - oo * 6;
        float w = W1[g];
        if (ii < 3) sW1A[(ii * 64 + p) * 64 + oo] = w;
        else        sW1B[((ii - 3) * 64 + p) * 64 + oo] = w;
    }
    if (t < 384) sW0[t] = W0[t];
    if (t < 64) {
        sB0s[t] = bn0_s[t]; sB0b[t] = bn0_b[t];
        sB1s[t] = bn1_s[t]; sB1b[t] = bn1_b[t];
    }
    if (t < 192) sWc[t] = Wc[t];
    if (t < 3) { sBnc[t] = bnc_s[t]; sBnc[4 + t] = bnc_b[t]; }

    // edge features: rows pt*20+k, layout [row][9]
    if (t < PTS * KNN_K) {
        int pt = t / KNN_K, k = t - pt * KNN_K;
        int gp = tile * PTS + pt;
        float e0 = 0.f, e1 = 0.f, e2 = 0.f, c0 = 0.f, c1 = 0.f, c2 = 0.f;
        if (gp < NPOINTS) {
            int b = gp >> 11, n = gp & (NPTS - 1);
            const float* xb = x + (size_t)b * 3 * NPTS;
            c0 = xb[n]; c1 = xb[NPTS + n]; c2 = xb[2 * NPTS + n];
            int j = g_knn[((size_t)b * NPTS + n) * KNN_K + k];
            e0 = xb[j] - c0;
            e1 = xb[NPTS + j] - c1;
            e2 = xb[2 * NPTS + j] - c2;
        }
        float* e = sE + t * EPAD;
        e[0] = e0; e[1] = e1; e[2] = e2;
        e[3] = c0; e[4] = c1; e[5] = c2;
    }
    __syncthreads();

    // MLP0: y[pt][p][k] = leaky((e . W0[p]) * bn0_s[p] + bn0_b[p])
    for (int v = t; v < PTS * CO * KNN_K; v += THR) {
        int pt = v / (CO * KNN_K);
        int rem = v - pt * (CO * KNN_K);
        int p = rem / KNN_K;
        int k = rem - p * KNN_K;
        const float* e = sE + (pt * KNN_K + k) * EPAD;
        const float* w = sW0 + p * 6;
        float d = e[0] * w[0];
        d = fmaf(e[1], w[1], d);
        d = fmaf(e[2], w[2], d);
        d = fmaf(e[3], w[3], d);
        d = fmaf(e[4], w[4], d);
        d = fmaf(e[5], w[5], d);
        float yv = fmaf(d, sB0s[p], sB0b[p]);
        yv = (yv >= 0.0f) ? yv : NEG_SLOPE * yv;
        sY[v] = yv;
    }
    __syncthreads();

    // main GEMM
    {
        const int pt = t >> 6;
        const int o  = t & 63;
        const float* ept = sE + (pt * KNN_K) * EPAD;
        const float cc0 = ept[3], cc1 = ept[4], cc2 = ept[5];
        float maxv = -INFINITY;

#pragma unroll
        for (int half = 0; half < 2; half++) {
            // pack d pairs: dp[q][i] = {d_i[k0], d_i[k0+1]}, k0 = half*10 + 2q
            unsigned long long dp[5][3];
#pragma unroll
            for (int q = 0; q < 5; q++) {
                const float* r0 = ept + (half * 10 + 2 * q) * EPAD;
                const float* r1 = r0 + EPAD;
#pragma unroll
                for (int i = 0; i < 3; i++)
                    dp[q][i] = pack2(r0[i], r1[i]);
            }

            unsigned long long acc[5];
#pragma unroll
            for (int q = 0; q < 5; q++) acc[q] = 0ull;

            const float* ybase = sY + (pt * CO) * KNN_K + half * 10;

#pragma unroll 2
            for (int p = 0; p < CO; p++) {
                const float* wa = sW1A + p * 64 + o;
                const float* wb = sW1B + p * 64 + o;
                float a0 = wa[0], a1 = wa[4096], a2 = wa[8192];
                float qv = wb[0] * cc0;
                qv = fmaf(wb[4096], cc1, qv);
                qv = fmaf(wb[8192], cc2, qv);
                unsigned long long a0d = dup2(a0);
                unsigned long long a1d = dup2(a1);
                unsigned long long a2d = dup2(a2);
                unsigned long long qd  = dup2(qv);

                const unsigned long long* yp =
                    (const unsigned long long*)(ybase + p * KNN_K);
                unsigned long long y0 = yp[0], y1 = yp[1], y2 = yp[2],
                                   y3 = yp[3], y4 = yp[4];

                unsigned long long t0 = qd, t1 = qd, t2 = qd, t3 = qd, t4 = qd;
                ffma2(t0, a0d, dp[0][0]); ffma2(t0, a1d, dp[0][1]); ffma2(t0, a2d, dp[0][2]);
                ffma2(t1, a0d, dp[1][0]); ffma2(t1, a1d, dp[1][1]); ffma2(t1, a2d, dp[1][2]);
                ffma2(t2, a0d, dp[2][0]); ffma2(t2, a1d, dp[2][1]); ffma2(t2, a2d, dp[2][2]);
                ffma2(t3, a0d, dp[3][0]); ffma2(t3, a1d, dp[3][1]); ffma2(t3, a2d, dp[3][2]);
                ffma2(t4, a0d, dp[4][0]); ffma2(t4, a1d, dp[4][1]); ffma2(t4, a2d, dp[4][2]);
                ffma2(acc[0], y0, t0);
                ffma2(acc[1], y1, t1);
                ffma2(acc[2], y2, t2);
                ffma2(acc[3], y3, t3);
                ffma2(acc[4], y4, t4);
            }

#pragma unroll
            for (int q = 0; q < 5; q++) {
                float lo, hi;
                unpack2(lo, hi, acc[q]);
                maxv = fmaxf(maxv, lo);
                maxv = fmaxf(maxv, hi);
            }
        }

        float vv = fmaf(maxv, sB1s[o], sB1b[o]);
        vv = (vv >= 0.0f) ? vv : NEG_SLOPE * vv;
        sX1[pt * 64 + o] = vv;
    }
    __syncthreads();

    // head
    if (t < PTS * 3) {
        int pt = t / 3, c = t - pt * 3;
        int gp = tile * PTS + pt;
        if (gp < NPOINTS) {
            int b = gp >> 11, n = gp & (NPTS - 1);
            const float* x1 = sX1 + pt * 64;
            const float* w = sWc + c * 64;
            float d = 0.0f;
#pragma unroll
            for (int o = 0; o < 64; o++) d = fmaf(x1[o], w[o], d);
            float z = fmaf(d, sBnc[c], sBnc[4 + c]);
            z = (z >= 0.0f) ? z : NEG_SLOPE * z;
            outp[((size_t)b * 3 + c) * NPTS + n] = z;
        }
    }
}

// ---------------------------------------------------------------------------
extern "C" void kernel_launch(void* const* d_in, const int* in_sizes, int n_in,
                              void* d_out, int out_size)
{
    const float* x     = (const float*)d_in[0];
    const float* W0    = (const float*)d_in[1];
    const float* bn0_s = (const float*)d_in[2];
    const float* bn0_b = (const float*)d_in[3];
    const float* W1    = (const float*)d_in[4];
    const float* bn1_s = (const float*)d_in[5];
    const float* bn1_b = (const float*)d_in[6];
    const float* Wc    = (const float*)d_in[7];
    const float* bnc_s = (const float*)d_in[8];
    const float* bnc_b = (const float*)d_in[9];
    float* outp = (float*)d_out;

    cudaFuncSetAttribute(knn_kernel,
                         cudaFuncAttributeMaxDynamicSharedMemorySize, KNN_SMEM_BYTES);
    cudaFuncSetAttribute(edge_kernel,
                         cudaFuncAttributeMaxDynamicSharedMemorySize, SMEM_BYTES);

    knn_kernel<<<BATCH * 32, KNN_THR, KNN_SMEM_BYTES>>>(x);
    edge_kernel<<<NTILES, THR, SMEM_BYTES>>>(
        x, W0, bn0_s, bn0_b, W1, bn1_s, bn1_b, Wc, bnc_s, bnc_b, outp);
}

// round 6
// speedup vs baseline: 2.0640x; 1.1483x over previous
#include <cuda_runtime.h>
#include <math.h>
#include <stdint.h>

#define NEG_SLOPE 0.2f
#define KNN_K 20
#define BATCH 8
#define NPTS 2048
#define CO 64
#define CIN 6
#define ROWS 384
#define NPOINTS (BATCH * NPTS)

__device__ int g_knn[NPOINTS * KNN_K];

typedef unsigned long long u64;

__device__ __forceinline__ void ffma2(u64& d, u64 a, u64 b) {
    asm("fma.rn.f32x2 %0, %1, %2, %0;" : "+l"(d) : "l"(a), "l"(b));
}
__device__ __forceinline__ u64 dup2(float w) {
    u64 r;
    asm("mov.b64 %0, {%1, %1};" : "=l"(r) : "f"(w));
    return r;
}
__device__ __forceinline__ u64 pack2(float lo, float hi) {
    u64 r;
    asm("mov.b64 %0, {%1, %2};" : "=l"(r) : "f"(lo), "f"(hi));
    return r;
}
__device__ __forceinline__ void unpack2(float& lo, float& hi, u64 v) {
    asm("mov.b64 {%0, %1}, %2;" : "=f"(lo), "=f"(hi) : "l"(v));
}

// ===========================================================================
// Kernel 1: KNN via value-only top-20 (FMNMX chain) + threshold rescan.
// 256 blocks x 256 threads; 64 points/block, 4 segment-lanes per point.
// Output: g_knn holds the exact top-20 SET (order arbitrary; consumer is
// max over k, which is permutation-invariant).
// ===========================================================================
#define KNN_THR 256
#define KNN_PPB 64
#define KSEG 4
#define SEGLEN (NPTS / KSEG)
#define CAND_CAP 32

#define KOFF_P     0                              // float4[2048] -> 8192 floats
#define KOFF_LIST  (NPTS * 4)                     // [64][4][20] = 5120
#define KOFF_TAU   (KOFF_LIST + KNN_PPB * KSEG * KNN_K)   // 64
#define KOFF_CNT   (KOFF_TAU + KNN_PPB)           // 64 ints
#define KOFF_CD    (KOFF_CNT + KNN_PPB)           // [64][32] floats
#define KOFF_CJ    (KOFF_CD + KNN_PPB * CAND_CAP) // [64][32] ints
#define KNN_SMEM_FLOATS (KOFF_CJ + KNN_PPB * CAND_CAP)
#define KNN_SMEM_BYTES (KNN_SMEM_FLOATS * 4)

__global__ __launch_bounds__(KNN_THR) void knn_kernel(const float* __restrict__ x) {
    extern __shared__ float ksm[];
    float4* sP   = (float4*)(ksm + KOFF_P);
    float* sList = ksm + KOFF_LIST;
    float* sTau  = ksm + KOFF_TAU;
    int*   sCnt  = (int*)(ksm + KOFF_CNT);
    float* sCd   = ksm + KOFF_CD;
    int*   sCj   = (int*)(ksm + KOFF_CJ);

    const int b = blockIdx.x >> 5;
    const int chunk = blockIdx.x & 31;
    const float* xb = x + (size_t)b * 3 * NPTS;

    const int t = threadIdx.x;
    for (int j = t; j < NPTS; j += KNN_THR) {
        float a0 = xb[j], a1 = xb[NPTS + j], a2 = xb[2 * NPTS + j];
        float xx = (a0 * a0 + a1 * a1) + a2 * a2;
        sP[j] = make_float4(a0, a1, a2, xx);
    }
    if (t < KNN_PPB) sCnt[t] = 0;
    __syncthreads();

    const int s  = t >> 6;        // segment (warp-uniform)
    const int pp = t & 63;
    const int i  = (chunk << 6) + pp;

    float4 cv = sP[i];
    const float c0 = cv.x, c1 = cv.y, c2 = cv.z, cxx = cv.w;

    // ---- Phase A: value-only sorted top-20 ----
    float v[KNN_K];
#pragma unroll
    for (int k = 0; k < KNN_K; k++) v[k] = -INFINITY;

    const int j0 = s * SEGLEN;
#pragma unroll 4
    for (int jj = 0; jj < SEGLEN; jj++) {
        int j = j0 + jj;
        float4 p4 = sP[j];
        float d = c0 * p4.x;
        d = fmaf(c1, p4.y, d);
        d = fmaf(c2, p4.z, d);
        d = 2.0f * d - cxx - p4.w;
        if (d > v[KNN_K - 1]) {
            float c = d;
#pragma unroll
            for (int k = 0; k < KNN_K; k++) {
                float nv = fmaxf(v[k], c);
                c = fminf(v[k], c);
                v[k] = nv;
            }
        }
    }
    {
        float* lp = sList + (pp * KSEG + s) * KNN_K;
#pragma unroll
        for (int k = 0; k < KNN_K; k++) lp[k] = v[k];
    }
    __syncthreads();

    // ---- merge: seg-0 lanes fold in the other 3 lists -> tau ----
    if (s == 0) {
        for (int ss = 1; ss < KSEG; ss++) {
            const float* lp = sList + (pp * KSEG + ss) * KNN_K;
#pragma unroll
            for (int k = 0; k < KNN_K; k++) {
                float d = lp[k];
                if (d > v[KNN_K - 1]) {
                    float c = d;
#pragma unroll
                    for (int q = 0; q < KNN_K; q++) {
                        float nv = fmaxf(v[q], c);
                        c = fminf(v[q], c);
                        v[q] = nv;
                    }
                }
            }
        }
        sTau[pp] = v[KNN_K - 1];
    }
    __syncthreads();

    // ---- Phase B: rescan, collect all j with d >= tau ----
    {
        const float tau = sTau[pp];
#pragma unroll 4
        for (int jj = 0; jj < SEGLEN; jj++) {
            int j = j0 + jj;
            float4 p4 = sP[j];
            float d = c0 * p4.x;
            d = fmaf(c1, p4.y, d);
            d = fmaf(c2, p4.z, d);
            d = 2.0f * d - cxx - p4.w;
            if (d >= tau) {
                int pos = atomicAdd(&sCnt[pp], 1);
                if (pos < CAND_CAP) {
                    sCd[pp * CAND_CAP + pos] = d;
                    sCj[pp * CAND_CAP + pos] = j;
                }
            }
        }
    }
    __syncthreads();

    // ---- exact selection: top-20 by (d desc, j asc) ----
    if (t < KNN_PPB) {
        int cnt = sCnt[t];
        if (cnt > CAND_CAP) cnt = CAND_CAP;
        float* cd = sCd + t * CAND_CAP;
        int*   cj = sCj + t * CAND_CAP;
        int* out = g_knn + ((size_t)b * NPTS + (chunk << 6) + t) * KNN_K;
        for (int slot = 0; slot < KNN_K; slot++) {
            float bd = -INFINITY; int bj = 0x7FFFFFFF, bi = 0;
            for (int q = 0; q < cnt; q++) {
                float d = cd[q]; int j = cj[q];
                bool better = (d > bd) || (d == bd && j < bj);
                if (better) { bd = d; bj = j; bi = q; }
            }
            out[slot] = bj;
            cd[bi] = -INFINITY;
        }
    }
}

// ===========================================================================
// Kernel 2: fused edge kernel, G-form c-folded bilinear GEMM (f32x2).
// 12 points/block, 768 threads; thread t: pt = t>>6, o = t&63.
// G_i[kpair] = sum_p y[k,p]*W1A_i[p,o]  (i=0..2),  Gq = sum_p y[k,p]*q[p,o],
//   q[p,o] = sum_i W1B_i[p,o]*c_i ;  out = Gq + sum_i d_i[k]*G_i.
// max over k BEFORE bn1+leaky (exact: bn1_s > 0).
// ===========================================================================
#define PTS 12
#define THR 768
#define NTILES ((NPOINTS + PTS - 1) / PTS)

#define EPAD 9

#define F_W1V  0                       // [p][o][6] = 24576
#define F_Y    (F_W1V + 24576)         // [12pt][64p][20k] = 15360
#define F_E    (F_Y + 15360)           // [12*20][9] = 2160
#define F_W0   (F_E + 2160)            // 384
#define F_B0S  (F_W0 + 384)
#define F_B0B  (F_B0S + 64)
#define F_B1S  (F_B0B + 64)
#define F_B1B  (F_B1S + 64)
#define F_WC   (F_B1B + 64)            // 192
#define F_BNC  (F_WC + 192)            // 8
#define F_X1   (F_BNC + 8)             // 768
#define SMEM_FLOATS (F_X1 + 768)
#define SMEM_BYTES (SMEM_FLOATS * 4)

__global__ __launch_bounds__(THR, 1) void edge_kernel(
    const float* __restrict__ x,
    const float* __restrict__ W0,
    const float* __restrict__ bn0_s, const float* __restrict__ bn0_b,
    const float* __restrict__ W1,
    const float* __restrict__ bn1_s, const float* __restrict__ bn1_b,
    const float* __restrict__ Wc,
    const float* __restrict__ bnc_s, const float* __restrict__ bnc_b,
    float* __restrict__ outp)
{
    extern __shared__ float sm[];
    float* sW1v = sm + F_W1V;
    float* sY   = sm + F_Y;
    float* sE   = sm + F_E;
    float* sW0  = sm + F_W0;
    float* sB0s = sm + F_B0S;
    float* sB0b = sm + F_B0B;
    float* sB1s = sm + F_B1S;
    float* sB1b = sm + F_B1B;
    float* sWc  = sm + F_WC;
    float* sBnc = sm + F_BNC;
    float* sX1  = sm + F_X1;

    const int t = threadIdx.x;
    const int tile = blockIdx.x;

    // stage W1: sW1v[(p*64 + oo)*6 + ii] = W1[(oo*6+ii)*64 + p]
    for (int g = t; g < ROWS * CO; g += THR) {
        int q = g >> 6;
        int p = g & 63;
        int oo = q / 6;
        int ii = q - oo * 6;
        sW1v[(p * 64 + oo) * 6 + ii] = W1[g];
    }
    if (t < 384) sW0[t] = W0[t];
    if (t < 64) {
        sB0s[t] = bn0_s[t]; sB0b[t] = bn0_b[t];
        sB1s[t] = bn1_s[t]; sB1b[t] = bn1_b[t];
    }
    if (t < 192) sWc[t] = Wc[t];
    if (t < 3) { sBnc[t] = bnc_s[t]; sBnc[4 + t] = bnc_b[t]; }

    // edge features: rows pt*20+k, layout [row][9]
    if (t < PTS * KNN_K) {
        int pt = t / KNN_K, k = t - pt * KNN_K;
        int gp = tile * PTS + pt;
        float e0 = 0.f, e1 = 0.f, e2 = 0.f, c0 = 0.f, c1 = 0.f, c2 = 0.f;
        if (gp < NPOINTS) {
            int b = gp >> 11, n = gp & (NPTS - 1);
            const float* xb = x + (size_t)b * 3 * NPTS;
            c0 = xb[n]; c1 = xb[NPTS + n]; c2 = xb[2 * NPTS + n];
            int j = g_knn[((size_t)b * NPTS + n) * KNN_K + k];
            e0 = xb[j] - c0;
            e1 = xb[NPTS + j] - c1;
            e2 = xb[2 * NPTS + j] - c2;
        }
        float* e = sE + t * EPAD;
        e[0] = e0; e[1] = e1; e[2] = e2;
        e[3] = c0; e[4] = c1; e[5] = c2;
    }
    __syncthreads();

    // MLP0: y[pt][p][k]
    for (int v = t; v < PTS * CO * KNN_K; v += THR) {
        int pt = v / (CO * KNN_K);
        int rem = v - pt * (CO * KNN_K);
        int p = rem / KNN_K;
        int k = rem - p * KNN_K;
        const float* e = sE + (pt * KNN_K + k) * EPAD;
        const float* w = sW0 + p * 6;
        float d = e[0] * w[0];
        d = fmaf(e[1], w[1], d);
        d = fmaf(e[2], w[2], d);
        d = fmaf(e[3], w[3], d);
        d = fmaf(e[4], w[4], d);
        d = fmaf(e[5], w[5], d);
        float yv = fmaf(d, sB0s[p], sB0b[p]);
        yv = (yv >= 0.0f) ? yv : NEG_SLOPE * yv;
        sY[v] = yv;
    }
    __syncthreads();

    // main GEMM
    {
        const int pt = t >> 6;
        const int o  = t & 63;
        const float* ept = sE + (pt * KNN_K) * EPAD;
        const float cc0 = ept[3], cc1 = ept[4], cc2 = ept[5];
        float maxv = -INFINITY;

#pragma unroll
        for (int half = 0; half < 2; half++) {
            u64 g0[5], g1[5], g2[5], gq[5];
#pragma unroll
            for (int q = 0; q < 5; q++) { g0[q] = 0; g1[q] = 0; g2[q] = 0; gq[q] = 0; }

            const float* yb = sY + (pt * CO) * KNN_K + half * 10;
            const float* wp = sW1v + o * 6;

#pragma unroll 2
            for (int p = 0; p < CO; p++) {
                u64 w01 = *(const u64*)(wp + 0);
                u64 w23 = *(const u64*)(wp + 2);
                u64 w45 = *(const u64*)(wp + 4);
                float a0, a1, a2, b0, b1, b2;
                unpack2(a0, a1, w01);
                unpack2(a2, b0, w23);
                unpack2(b1, b2, w45);
                float qv = b0 * cc0;
                qv = fmaf(b1, cc1, qv);
                qv = fmaf(b2, cc2, qv);
                u64 a0d = dup2(a0), a1d = dup2(a1), a2d = dup2(a2), qd = dup2(qv);

                const u64* yp = (const u64*)(yb + p * KNN_K);
                u64 y0 = yp[0], y1 = yp[1], y2 = yp[2], y3 = yp[3], y4 = yp[4];

                ffma2(g0[0], y0, a0d); ffma2(g1[0], y0, a1d); ffma2(g2[0], y0, a2d); ffma2(gq[0], y0, qd);
                ffma2(g0[1], y1, a0d); ffma2(g1[1], y1, a1d); ffma2(g2[1], y1, a2d); ffma2(gq[1], y1, qd);
                ffma2(g0[2], y2, a0d); ffma2(g1[2], y2, a1d); ffma2(g2[2], y2, a2d); ffma2(gq[2], y2, qd);
                ffma2(g0[3], y3, a0d); ffma2(g1[3], y3, a1d); ffma2(g2[3], y3, a2d); ffma2(gq[3], y3, qd);
                ffma2(g0[4], y4, a0d); ffma2(g1[4], y4, a1d); ffma2(g2[4], y4, a2d); ffma2(gq[4], y4, qd);

                wp += 384;
            }

#pragma unroll
            for (int q = 0; q < 5; q++) {
                const float* r0 = ept + (half * 10 + 2 * q) * EPAD;
                const float* r1 = r0 + EPAD;
                u64 d0 = pack2(r0[0], r1[0]);
                u64 d1 = pack2(r0[1], r1[1]);
                u64 d2 = pack2(r0[2], r1[2]);
                u64 acc = gq[q];
                ffma2(acc, d0, g0[q]);
                ffma2(acc, d1, g1[q]);
                ffma2(acc, d2, g2[q]);
                float lo, hi;
                unpack2(lo, hi, acc);
                maxv = fmaxf(maxv, lo);
                maxv = fmaxf(maxv, hi);
            }
        }

        float vv = fmaf(maxv, sB1s[o], sB1b[o]);
        vv = (vv >= 0.0f) ? vv : NEG_SLOPE * vv;
        sX1[pt * 64 + o] = vv;
    }
    __syncthreads();

    // head
    if (t < PTS * 3) {
        int pt = t / 3, c = t - pt * 3;
        int gp = tile * PTS + pt;
        if (gp < NPOINTS) {
            int b = gp >> 11, n = gp & (NPTS - 1);
            const float* x1 = sX1 + pt * 64;
            const float* w = sWc + c * 64;
            float d = 0.0f;
#pragma unroll
            for (int o = 0; o < 64; o++) d = fmaf(x1[o], w[o], d);
            float z = fmaf(d, sBnc[c], sBnc[4 + c]);
            z = (z >= 0.0f) ? z : NEG_SLOPE * z;
            outp[((size_t)b * 3 + c) * NPTS + n] = z;
        }
    }
}

// ---------------------------------------------------------------------------
extern "C" void kernel_launch(void* const* d_in, const int* in_sizes, int n_in,
                              void* d_out, int out_size)
{
    const float* x     = (const float*)d_in[0];
    const float* W0    = (const float*)d_in[1];
    const float* bn0_s = (const float*)d_in[2];
    const float* bn0_b = (const float*)d_in[3];
    const float* W1    = (const float*)d_in[4];
    const float* bn1_s = (const float*)d_in[5];
    const float* bn1_b = (const float*)d_in[6];
    const float* Wc    = (const float*)d_in[7];
    const float* bnc_s = (const float*)d_in[8];
    const float* bnc_b = (const float*)d_in[9];
    float* outp = (float*)d_out;

    cudaFuncSetAttribute(knn_kernel,
                         cudaFuncAttributeMaxDynamicSharedMemorySize, KNN_SMEM_BYTES);
    cudaFuncSetAttribute(edge_kernel,
                         cudaFuncAttributeMaxDynamicSharedMemorySize, SMEM_BYTES);

    knn_kernel<<<BATCH * 32, KNN_THR, KNN_SMEM_BYTES>>>(x);
    edge_kernel<<<NTILES, THR, SMEM_BYTES>>>(
        x, W0, bn0_s, bn0_b, W1, bn1_s, bn1_b, Wc, bnc_s, bnc_b, outp);
}